// round 2
// baseline (speedup 1.0000x reference)
#include <cuda_runtime.h>
#include <math.h>

// Problem constants
#define N_POS   131072          // 32 * 64 * 64 positions
#define KCODES  512
#define DDIM    64
#define NPAIR   256             // KCODES / 2
#define MAIN_BLOCKS  512
#define MAIN_THREADS 256
#define SMEM_BYTES (131072 + 2048 + 2048)   // epack + eN pairs + hist

// Scratch (device globals; no allocation allowed)
__device__ ulonglong2 g_epack[NPAIR * 32];   // [pair j][t] : t covers d=2t,2t+1; halves = (k=2j, k=2j+1), values = -2*e
__device__ float  g_eN[KCODES];
__device__ int    g_counts[KCODES];
__device__ double g_sse[MAIN_BLOCKS];

static __device__ __forceinline__ unsigned long long pack2(float lo, float hi) {
    unsigned long long r;
    asm("mov.b64 %0, {%1, %2};" : "=l"(r) : "f"(lo), "f"(hi));
    return r;
}
static __device__ __forceinline__ float lo2(unsigned long long v) {
    return __uint_as_float((unsigned int)v);
}
static __device__ __forceinline__ float hi2(unsigned long long v) {
    return __uint_as_float((unsigned int)(v >> 32));
}
static __device__ __forceinline__ unsigned long long ffma2(unsigned long long a,
                                                           unsigned long long b,
                                                           unsigned long long c) {
    unsigned long long d;
    asm("fma.rn.f32x2 %0, %1, %2, %3;" : "=l"(d) : "l"(a), "l"(b), "l"(c));
    return d;
}
static __device__ __forceinline__ unsigned long long fadd2(unsigned long long a,
                                                           unsigned long long b) {
    unsigned long long d;
    asm("add.rn.f32x2 %0, %1, %2;" : "=l"(d) : "l"(a), "l"(b));
    return d;
}

// ---------------------------------------------------------------------------
// Kernel 1: pack codebook (-2*e, pair-interleaved), eN = ||e||^2, zero counts
// ---------------------------------------------------------------------------
__global__ void prep_kernel(const float* __restrict__ e) {
    int tid = blockIdx.x * blockDim.x + threadIdx.x;   // 32*256 = 8192 threads
    if (tid < KCODES) {
        const float* row = e + tid * DDIM;
        float s = 0.f;
        #pragma unroll
        for (int d = 0; d < DDIM; ++d) s = fmaf(row[d], row[d], s);
        g_eN[tid] = s;
        g_counts[tid] = 0;
    }
    if (tid < NPAIR * 32) {
        int j = tid >> 5, t = tid & 31;
        int d0 = 2 * t, d1 = 2 * t + 1;
        float a0 = -2.f * e[(2 * j)     * DDIM + d0];
        float b0 = -2.f * e[(2 * j + 1) * DDIM + d0];
        float a1 = -2.f * e[(2 * j)     * DDIM + d1];
        float b1 = -2.f * e[(2 * j + 1) * DDIM + d1];
        ulonglong2 v;
        v.x = pack2(a0, b0);
        v.y = pack2(a1, b1);
        g_epack[tid] = v;
    }
}

// ---------------------------------------------------------------------------
// Kernel 2: per-position argmin over 512 codes + fused epilogue
// ---------------------------------------------------------------------------
__global__ __launch_bounds__(MAIN_THREADS, 1)
void vq_main_kernel(const float* __restrict__ z, float* __restrict__ out) {
    extern __shared__ char smem[];
    ulonglong2*         sE    = (ulonglong2*)smem;                       // 131072 B
    unsigned long long* sEN   = (unsigned long long*)(smem + 131072);    // 2048 B (eN pairs)
    int*                sHist = (int*)(smem + 131072 + 2048);            // 2048 B

    const int tid = threadIdx.x;

    // stage codebook into shared memory
    for (int i = tid; i < NPAIR * 32; i += MAIN_THREADS) sE[i] = g_epack[i];
    if (tid < NPAIR) sEN[tid] = pack2(g_eN[2 * tid], g_eN[2 * tid + 1]);
    for (int i = tid; i < KCODES; i += MAIN_THREADS) sHist[i] = 0;
    __syncthreads();

    const int p    = blockIdx.x * MAIN_THREADS + tid;   // position in [0, 131072)
    const int b    = p >> 12;                            // batch
    const int hw   = p & 4095;                           // h*64 + w
    const int zoff = b * 262144 + hw;                    // NCHW base; stride 4096 per d

    // load z vector, duplicate into f32x2 pairs, zsq in fp32 (any fp32 value works:
    // whole-ulp shifts of zsq preserve the reference's rounding grid for all k)
    unsigned long long zz[DDIM];
    float zsq = 0.f;
    #pragma unroll
    for (int d = 0; d < DDIM; ++d) {
        float zv = __ldg(z + zoff + d * 4096);
        zz[d] = pack2(zv, zv);
        zsq = fmaf(zv, zv, zsq);
    }
    const unsigned long long zsq2 = pack2(zsq, zsq);

    // argmin: dist_k = fl( fl(zsq + eN_k) + chain(-2*z.e_k) )
    // matches reference association (zsq + eN) - 2*dot with single large-magnitude add
    float best = __int_as_float(0x7f800000);   // +inf
    int bestk = 0;
    for (int j = 0; j < NPAIR; ++j) {
        const ulonglong2* ep = sE + j * 32;
        unsigned long long a0 = 0ull, a1 = 0ull;   // two independent chains: d 0..31, 32..63
        #pragma unroll
        for (int t = 0; t < 16; ++t) {
            ulonglong2 e0 = ep[t];
            ulonglong2 e1 = ep[t + 16];
            a0 = ffma2(zz[2 * t],      e0.x, a0);
            a0 = ffma2(zz[2 * t + 1],  e0.y, a0);
            a1 = ffma2(zz[32 + 2 * t], e1.x, a1);
            a1 = ffma2(zz[33 + 2 * t], e1.y, a1);
        }
        unsigned long long acc = fadd2(a0, a1);       // = -fl(2*dot) per half
        unsigned long long A   = fadd2(zsq2, sEN[j]); // fl(zsq + eN_k) per half
        unsigned long long dd  = fadd2(A, acc);
        float s0 = lo2(dd), s1 = hi2(dd);
        if (s0 < best) { best = s0; bestk = 2 * j; }      // strict <: first-index ties,
        if (s1 < best) { best = s1; bestk = 2 * j + 1; }  // matches jnp.argmin
    }

    // epilogue: histogram, z_q scatter (NCHW), SSE
    atomicAdd(&sHist[bestk], 1);
    const int jj = bestk >> 1;
    const int odd = bestk & 1;
    const ulonglong2* ep = sE + jj * 32;
    double sse = 0.0;
    float* o = out + 1 + zoff;                      // out[0] = loss, z_q at [1..]
    #pragma unroll
    for (int t = 0; t < 32; ++t) {
        ulonglong2 ev = ep[t];
        float q0 = -0.5f * (odd ? hi2(ev.x) : lo2(ev.x));   // recover e exactly (-0.5 * -2e)
        float q1 = -0.5f * (odd ? hi2(ev.y) : lo2(ev.y));
        o[(2 * t)     * 4096] = q0;
        o[(2 * t + 1) * 4096] = q1;
        float d0f = q0 - lo2(zz[2 * t]);
        float d1f = q1 - lo2(zz[2 * t + 1]);
        sse += (double)(d0f * d0f);
        sse += (double)(d1f * d1f);
    }

    // deterministic SSE reduction: warp shuffle -> smem -> per-block slot
    #pragma unroll
    for (int off = 16; off > 0; off >>= 1)
        sse += __shfl_down_sync(0xffffffffu, sse, off);
    __shared__ double wsum[MAIN_THREADS / 32];
    const int lane = tid & 31, wid = tid >> 5;
    if (lane == 0) wsum[wid] = sse;
    __syncthreads();   // also orders the sHist atomics above
    if (tid == 0) {
        double s = 0.0;
        #pragma unroll
        for (int i = 0; i < MAIN_THREADS / 32; ++i) s += wsum[i];
        g_sse[blockIdx.x] = s;
    }
    for (int i = tid; i < KCODES; i += MAIN_THREADS) {
        int c = sHist[i];
        if (c) atomicAdd(&g_counts[i], c);   // integer: deterministic
    }
}

// ---------------------------------------------------------------------------
// Kernel 3: perplexity + loss
// ---------------------------------------------------------------------------
__global__ void finalize_kernel(float* __restrict__ out, int out_size) {
    __shared__ double sh[KCODES];
    const int t = threadIdx.x;   // 512 threads
    double em = (double)g_counts[t] * (1.0 / 131072.0);
    double x = em + 1e-10;
    sh[t] = x * log(x);
    __syncthreads();
    for (int s = KCODES / 2; s > 0; s >>= 1) {
        if (t < s) sh[t] += sh[t + s];
        __syncthreads();
    }
    if (t == 0) {
        double ent = sh[0];
        double sse = 0.0;
        for (int i = 0; i < MAIN_BLOCKS; ++i) sse += g_sse[i];   // fixed order: deterministic
        // mean over ALL elements: B*H*W*D = 32*64*64*64 = 8388608  (R1 fix: was /2097152 -> loss 4x too big)
        double mse = sse / 8388608.0;
        out[0]            = (float)(1.25 * mse);   // codebook + 0.25*commitment
        out[out_size - 1] = (float)exp(-ent);      // perplexity
    }
}

// ---------------------------------------------------------------------------
extern "C" void kernel_launch(void* const* d_in, const int* in_sizes, int n_in,
                              void* d_out, int out_size) {
    const float* z = (const float*)d_in[0];
    const float* e = (const float*)d_in[1];
    // defensive: metadata order should be (z, e_weight); swap if sizes say otherwise
    if (n_in >= 2 && in_sizes[0] == KCODES * DDIM && in_sizes[1] == N_POS * 16) {
        const float* tmp = z; z = e; e = tmp;
    }
    cudaFuncSetAttribute(vq_main_kernel,
                         cudaFuncAttributeMaxDynamicSharedMemorySize, SMEM_BYTES);

    prep_kernel<<<32, 256>>>(e);
    vq_main_kernel<<<MAIN_BLOCKS, MAIN_THREADS, SMEM_BYTES>>>(z, (float*)d_out);
    finalize_kernel<<<1, KCODES>>>((float*)d_out, out_size);
}

// round 3
// speedup vs baseline: 1.0876x; 1.0876x over previous
#include <cuda_runtime.h>
#include <math.h>

// Problem constants
#define N_POS   131072          // 32 * 64 * 64 positions
#define KCODES  512
#define DDIM    64
#define MAIN_BLOCKS  256
#define MAIN_THREADS 512
#define SMEM_BYTES (131072 + 2048 + 2048)   // epack + eN + hist

// Scratch (device globals; zero-initialized at load; finalize re-zeros counts each run)
__device__ int    g_counts[KCODES];
__device__ double g_sse[MAIN_BLOCKS];

static __device__ __forceinline__ unsigned long long pack2(float lo, float hi) {
    unsigned long long r;
    asm("mov.b64 %0, {%1, %2};" : "=l"(r) : "f"(lo), "f"(hi));
    return r;
}
static __device__ __forceinline__ float lo2(unsigned long long v) {
    return __uint_as_float((unsigned int)v);
}
static __device__ __forceinline__ float hi2(unsigned long long v) {
    return __uint_as_float((unsigned int)(v >> 32));
}
static __device__ __forceinline__ unsigned long long ffma2(unsigned long long a,
                                                           unsigned long long b,
                                                           unsigned long long c) {
    unsigned long long d;
    asm("fma.rn.f32x2 %0, %1, %2, %3;" : "=l"(d) : "l"(a), "l"(b), "l"(c));
    return d;
}
static __device__ __forceinline__ unsigned long long fadd2(unsigned long long a,
                                                           unsigned long long b) {
    unsigned long long d;
    asm("add.rn.f32x2 %0, %1, %2;" : "=l"(d) : "l"(a), "l"(b));
    return d;
}

// ---------------------------------------------------------------------------
// Main kernel: 256 blocks x 512 threads, 1 position per thread.
// smem codebook layout: sE[k*16+q] = ulonglong2 { (-2e[k][4q],-2e[k][4q+1]),
//                                                 (-2e[k][4q+2],-2e[k][4q+3]) }
// z packed over adjacent dims -> zz is 32 ulonglong = 64 registers.
// ---------------------------------------------------------------------------
__global__ __launch_bounds__(MAIN_THREADS, 1)
void vq_main_kernel(const float* __restrict__ z, const float* __restrict__ e,
                    float* __restrict__ out) {
    extern __shared__ char smem[];
    ulonglong2* sE    = (ulonglong2*)smem;                    // 131072 B
    float*      sEN   = (float*)(smem + 131072);              // 2048 B
    int*        sHist = (int*)(smem + 131072 + 2048);         // 2048 B

    const int tid = threadIdx.x;
    const int p    = blockIdx.x * MAIN_THREADS + tid;   // [0, 131072)
    const int b    = p >> 12;
    const int hw   = p & 4095;
    const int zoff = b * 262144 + hw;                   // NCHW; stride 4096 per d

    // issue z loads early (independent of smem pack; overlaps LDG latency)
    unsigned long long zz[DDIM / 2];
    float zsq = 0.f;
    #pragma unroll
    for (int i = 0; i < 32; ++i) {
        float f0 = __ldg(z + zoff + (2 * i)     * 4096);
        float f1 = __ldg(z + zoff + (2 * i + 1) * 4096);
        zz[i] = pack2(f0, f1);
        zsq = fmaf(f0, f0, zsq);
        zsq = fmaf(f1, f1, zsq);
    }

    // cooperative pack of codebook into smem (-2*e), eN, hist zero
    for (int i = tid; i < KCODES * 16; i += MAIN_THREADS) {
        int k = i >> 4, q = i & 15;
        float4 v = *(const float4*)(e + k * DDIM + q * 4);
        ulonglong2 w;
        w.x = pack2(-2.f * v.x, -2.f * v.y);
        w.y = pack2(-2.f * v.z, -2.f * v.w);
        sE[i] = w;
    }
    {
        const float4* row = (const float4*)(e + tid * DDIM);  // tid < 512 == KCODES
        float s = 0.f;
        #pragma unroll
        for (int q = 0; q < 16; ++q) {
            float4 v = row[q];
            s = fmaf(v.x, v.x, s); s = fmaf(v.y, v.y, s);
            s = fmaf(v.z, v.z, s); s = fmaf(v.w, v.w, s);
        }
        sEN[tid] = s;
        sHist[tid] = 0;
    }
    __syncthreads();

    // argmin over 512 codes: score_k = fl( fl(zsq + eN_k) + dot(-2e_k, z) )
    float best = __int_as_float(0x7f800000);
    int bestk = 0;
    #pragma unroll 2
    for (int k = 0; k < KCODES; ++k) {
        const ulonglong2* ep = sE + k * 16;
        unsigned long long c0 = 0ull, c1 = 0ull;   // two chains for ILP
        #pragma unroll
        for (int q = 0; q < 16; ++q) {
            ulonglong2 ev = ep[q];
            c0 = ffma2(zz[2 * q],     ev.x, c0);
            c1 = ffma2(zz[2 * q + 1], ev.y, c1);
        }
        unsigned long long s2 = fadd2(c0, c1);
        float s  = lo2(s2) + hi2(s2);              // horizontal add (reg-pair halves)
        float sc = (zsq + sEN[k]) + s;             // large-magnitude add last, as reference
        if (sc < best) { best = sc; bestk = k; }   // strict <: first-index ties
    }

    // epilogue: histogram, z_q scatter (NCHW), SSE
    atomicAdd(&sHist[bestk], 1);
    const ulonglong2* ep = sE + bestk * 16;
    double sse = 0.0;
    float* o = out + 1 + zoff;                     // out[0] = loss, z_q at [1..]
    #pragma unroll
    for (int q = 0; q < 16; ++q) {
        ulonglong2 ev = ep[q];
        float q0 = -0.5f * lo2(ev.x);              // recover e exactly
        float q1 = -0.5f * hi2(ev.x);
        float q2 = -0.5f * lo2(ev.y);
        float q3 = -0.5f * hi2(ev.y);
        o[(4 * q)     * 4096] = q0;
        o[(4 * q + 1) * 4096] = q1;
        o[(4 * q + 2) * 4096] = q2;
        o[(4 * q + 3) * 4096] = q3;
        float d0 = q0 - lo2(zz[2 * q]);
        float d1 = q1 - hi2(zz[2 * q]);
        float d2 = q2 - lo2(zz[2 * q + 1]);
        float d3 = q3 - hi2(zz[2 * q + 1]);
        sse += (double)(d0 * d0) + (double)(d1 * d1);
        sse += (double)(d2 * d2) + (double)(d3 * d3);
    }

    // deterministic SSE reduction: warp shuffle -> smem -> per-block slot
    #pragma unroll
    for (int off = 16; off > 0; off >>= 1)
        sse += __shfl_down_sync(0xffffffffu, sse, off);
    __shared__ double wsum[MAIN_THREADS / 32];
    const int lane = tid & 31, wid = tid >> 5;
    if (lane == 0) wsum[wid] = sse;
    __syncthreads();   // also orders the sHist atomics above
    if (tid == 0) {
        double s = 0.0;
        #pragma unroll
        for (int i = 0; i < MAIN_THREADS / 32; ++i) s += wsum[i];
        g_sse[blockIdx.x] = s;
    }
    if (tid < KCODES) {
        int c = sHist[tid];
        if (c) atomicAdd(&g_counts[tid], c);       // integer: deterministic
    }
}

// ---------------------------------------------------------------------------
// Finalize: perplexity + loss; re-zeros g_counts for the next graph replay
// ---------------------------------------------------------------------------
__global__ void finalize_kernel(float* __restrict__ out, int out_size) {
    __shared__ double sh[KCODES];
    const int t = threadIdx.x;   // 512 threads
    double em = (double)g_counts[t] * (1.0 / 131072.0);
    g_counts[t] = 0;             // replay-safe reset after consuming
    double x = em + 1e-10;
    sh[t] = x * log(x);
    __syncthreads();
    for (int s = KCODES / 2; s > 0; s >>= 1) {
        if (t < s) sh[t] += sh[t + s];
        __syncthreads();
    }
    double ent = sh[0];
    __syncthreads();
    // parallel SSE reduction over 256 block partials (fixed tree: deterministic)
    sh[t] = (t < MAIN_BLOCKS) ? g_sse[t] : 0.0;
    __syncthreads();
    for (int s = KCODES / 2; s > 0; s >>= 1) {
        if (t < s) sh[t] += sh[t + s];
        __syncthreads();
    }
    if (t == 0) {
        double mse = sh[0] / 8388608.0;            // mean over B*H*W*D elements
        out[0]            = (float)(1.25 * mse);   // codebook + 0.25*commitment
        out[out_size - 1] = (float)exp(-ent);      // perplexity
    }
}

// ---------------------------------------------------------------------------
extern "C" void kernel_launch(void* const* d_in, const int* in_sizes, int n_in,
                              void* d_out, int out_size) {
    const float* z = (const float*)d_in[0];
    const float* e = (const float*)d_in[1];
    if (n_in >= 2 && in_sizes[0] == KCODES * DDIM && in_sizes[1] == N_POS * 16) {
        const float* tmp = z; z = e; e = tmp;      // defensive input-order swap
    }
    cudaFuncSetAttribute(vq_main_kernel,
                         cudaFuncAttributeMaxDynamicSharedMemorySize, SMEM_BYTES);

    vq_main_kernel<<<MAIN_BLOCKS, MAIN_THREADS, SMEM_BYTES>>>(z, e, (float*)d_out);
    finalize_kernel<<<1, KCODES>>>((float*)d_out, out_size);
}